// round 6
// baseline (speedup 1.0000x reference)
#include <cuda_runtime.h>
#include <cstdint>
#include <math.h>

#define DIM 256
#define TM 128
#define THREADS 256
#define KC 32
#define STAGES 4
#define NJOBS 32                 // 4 passes x 8 chunks

#define PX 36                    // X smem row stride (floats): 36%32==4 -> LDSM conflict-free
#define PW 36                    // Wt smem row stride
#define GW 256                   // g_Wt gmem row stride
#define XS_FLOATS (128 * PX)     // 4608
#define WS_FLOATS (256 * PW)     // 9216
#define BUF_FLOATS (XS_FLOATS + WS_FLOATS)       // 13824 -> 55296 B
#define BUF_BYTES (BUF_FLOATS * 4)
#define SMEM_BYTES (STAGES * BUF_BYTES)          // 221184

__device__ float g_Wt[4][256 * GW];   // [n][k], transposed + tf32-rna-rounded

__device__ __forceinline__ uint32_t smem_u32(const void* p) {
    uint32_t a;
    asm("{ .reg .u64 t; cvta.to.shared.u64 t, %1; cvt.u32.u64 %0, t; }" : "=r"(a) : "l"(p));
    return a;
}
__device__ __forceinline__ void cp16(uint32_t s, const float* g) {
    asm volatile("cp.async.cg.shared.global [%0], [%1], 16;" :: "r"(s), "l"(g));
}
#define CP_COMMIT() asm volatile("cp.async.commit_group;" ::: "memory")
#define CP_WAIT(n)  asm volatile("cp.async.wait_group %0;" :: "n"(n) : "memory")

__device__ __forceinline__ uint32_t to_tf32(float x) {
    uint32_t r;
    asm("cvt.rna.tf32.f32 %0, %1;" : "=r"(r) : "f"(x));
    return r;
}
__device__ __forceinline__ void ldsm4(uint32_t* r, uint32_t addr) {
    asm volatile("ldmatrix.sync.aligned.m8n8.x4.shared.b16 {%0,%1,%2,%3}, [%4];"
                 : "=r"(r[0]), "=r"(r[1]), "=r"(r[2]), "=r"(r[3]) : "r"(addr));
}
__device__ __forceinline__ void mma8(float* c, const uint32_t* a, const uint32_t* b) {
    asm volatile(
        "mma.sync.aligned.m16n8k8.row.col.f32.tf32.tf32.f32 "
        "{%0,%1,%2,%3}, {%4,%5,%6,%7}, {%8,%9}, {%0,%1,%2,%3};"
        : "+f"(c[0]), "+f"(c[1]), "+f"(c[2]), "+f"(c[3])
        : "r"(a[0]), "r"(a[1]), "r"(a[2]), "r"(a[3]), "r"(b[0]), "r"(b[1]));
}

// ---- one KC=32 chunk: acc(32x128 warptile) += X @ W ----
// a_base/b_base: per-lane LDSM addresses for mt=0 / nt2=0 at ks=0.
template <bool SCALE>
__device__ __forceinline__ void gemm_chunk(uint32_t a_base, uint32_t b_base,
                                           float (&acc)[2][16][4],
                                           const float (&sc)[2][2]) {
#pragma unroll
    for (int ks = 0; ks < 4; ++ks) {
        uint32_t ua[2][4];
        ldsm4(ua[0], a_base + ks * 32);
        ldsm4(ua[1], a_base + 16 * PX * 4 + ks * 32);
        if (SCALE) {
#pragma unroll
            for (int mt = 0; mt < 2; ++mt) {
                ua[mt][0] = __float_as_uint(__uint_as_float(ua[mt][0]) * sc[mt][0]);
                ua[mt][1] = __float_as_uint(__uint_as_float(ua[mt][1]) * sc[mt][1]);
                ua[mt][2] = __float_as_uint(__uint_as_float(ua[mt][2]) * sc[mt][0]);
                ua[mt][3] = __float_as_uint(__uint_as_float(ua[mt][3]) * sc[mt][1]);
            }
        }
#pragma unroll
        for (int nt2 = 0; nt2 < 8; ++nt2) {
            uint32_t b[4];                              // b0/b1 for nt=2*nt2, 2*nt2+1
            ldsm4(b, b_base + nt2 * (16 * PW * 4) + ks * 32);
            mma8(acc[0][2 * nt2],     ua[0], b);
            mma8(acc[1][2 * nt2],     ua[1], b);
            mma8(acc[0][2 * nt2 + 1], ua[0], b + 2);
            mma8(acc[1][2 * nt2 + 1], ua[1], b + 2);
        }
    }
}

__device__ __forceinline__ void zero_acc(float (&acc)[2][16][4]) {
#pragma unroll
    for (int mt = 0; mt < 2; ++mt)
#pragma unroll
        for (int nt = 0; nt < 16; ++nt)
#pragma unroll
            for (int q = 0; q < 4; ++q) acc[mt][nt][q] = 0.f;
}

__device__ __forceinline__ void gate_dot(const float* __restrict__ Xo,
                                         const float (&acc)[2][16][4], int g,
                                         int wm, int wn, int lq, int lr,
                                         float (*s_g)[2][128]) {
    float pr[2][2] = {{0.f, 0.f}, {0.f, 0.f}};
#pragma unroll
    for (int mt = 0; mt < 2; ++mt) {
        const int r0 = wm * 32 + mt * 16 + lq;
#pragma unroll
        for (int nt = 0; nt < 16; ++nt) {
            const int cb = wn * 128 + nt * 8 + lr * 2;
            float2 v0 = *reinterpret_cast<const float2*>(Xo + (size_t)r0 * DIM + cb);
            float2 v1 = *reinterpret_cast<const float2*>(Xo + (size_t)(r0 + 8) * DIM + cb);
            pr[mt][0] += acc[mt][nt][0] * v0.x + acc[mt][nt][1] * v0.y;
            pr[mt][1] += acc[mt][nt][2] * v1.x + acc[mt][nt][3] * v1.y;
        }
    }
#pragma unroll
    for (int off = 1; off <= 2; off <<= 1)
#pragma unroll
        for (int mt = 0; mt < 2; ++mt) {
            pr[mt][0] += __shfl_xor_sync(0xFFFFFFFFu, pr[mt][0], off);
            pr[mt][1] += __shfl_xor_sync(0xFFFFFFFFu, pr[mt][1], off);
        }
    if (lr == 0) {
#pragma unroll
        for (int mt = 0; mt < 2; ++mt) {
            s_g[g][wn][wm * 32 + mt * 16 + lq] = pr[mt][0];
            s_g[g][wn][wm * 32 + mt * 16 + lq + 8] = pr[mt][1];
        }
    }
}

__global__ void __launch_bounds__(THREADS, 1)
fused_mma_kernel(const float* __restrict__ i0, const float* __restrict__ i1,
                 float* __restrict__ out) {
    extern __shared__ float dyn[];
    __shared__ float s_g[2][2][128];
    __shared__ float s_sc[2][128];

    const int tid = threadIdx.x;
    const int l = tid & 31, w = tid >> 5;
    const int wm = w >> 1, wn = w & 1;
    const int lq = l >> 2, lr = l & 3;
    const size_t rowbase = (size_t)blockIdx.x * TM;
    const float* X0g = i0 + rowbase * DIM;
    const float* X1g = i1 + rowbase * DIM;
    const uint32_t sb = smem_u32(dyn);

    // per-lane LDSM tile addressing
    const int arow = ((l >> 3) & 1) * 8 + (l & 7);   // A: t0/t2 rows 0-7, t1/t3 rows 8-15
    const int acg  = (l >> 4) & 1;                   //    t0/t1 cols 0-3, t2/t3 cols 4-7
    const int brow = ((l >> 4) & 1) * 8 + (l & 7);   // B: t0/t1 n 0-7, t2/t3 n 8-15
    const int bcg  = (l >> 3) & 1;
    const uint32_t a_off = (uint32_t)((wm * 32 + arow) * PX + acg * 4) * 4;
    const uint32_t b_off = (uint32_t)(XS_FLOATS + (wn * 128 + brow) * PW + bcg * 4) * 4;

    // jobs 0..31: pass p=j>>3, chunk c=j&7
    //  p0: A=X1,B=attn1 -> g0 dot X0    p1: A=X0,B=attn2 -> g1 dot X1
    //  p2: A=X0,B=W1 (scale s0)         p3: A=X1,B=W2 (scale s1)
    auto stage = [&](int j) {
        const int p = j >> 3, c = j & 7;
        const float* As = (p == 0 || p == 3) ? X1g : X0g;
        const float* Bs = g_Wt[p];
        const uint32_t base = sb + (uint32_t)(j & 3) * BUF_BYTES;
#pragma unroll
        for (int t = 0; t < 4; ++t) {          // X chunk: 128 x 32
            const int id = tid + t * THREADS;
            const int r = id >> 3, c4 = (id & 7) << 2;
            cp16(base + (uint32_t)(r * PX + c4) * 4, As + (size_t)r * DIM + c * 32 + c4);
        }
#pragma unroll
        for (int t = 0; t < 8; ++t) {          // Wt chunk: 256 n x 32 k
            const int id = tid + t * THREADS;
            const int n = id >> 3, k4 = (id & 7) << 2;
            cp16(base + (uint32_t)(XS_FLOATS + n * PW + k4) * 4,
                 Bs + (size_t)n * GW + c * 32 + k4);
        }
        CP_COMMIT();
    };

    float acc[2][16][4];
    zero_acc(acc);
    float sc[2][2] = {{1.f, 1.f}, {1.f, 1.f}};

    stage(0); stage(1); stage(2);

    for (int j = 0; j < NJOBS; ++j) {
        const int rem = NJOBS - 1 - j;
        if (rem >= 2)      { CP_WAIT(2); }
        else if (rem == 1) { CP_WAIT(1); }
        else               { CP_WAIT(0); }
        __syncthreads();                       // buf j ready; all reads of buf j-1 done
        if (j + 3 < NJOBS) stage(j + 3);       // writes buf (j-1)&3: safe after barrier

        const uint32_t base = sb + (uint32_t)(j & 3) * BUF_BYTES;
        if (j >= 16) gemm_chunk<true>(base + a_off, base + b_off, acc, sc);
        else         gemm_chunk<false>(base + a_off, base + b_off, acc, sc);

        if (j == 7) {                          // g0 = rowdot(U0, X0)
            gate_dot(X0g, acc, 0, wm, wn, lq, lr, s_g);
            zero_acc(acc);
        }
        if (j == 15) {                         // g1; sigmoid; load s0 scales
            gate_dot(X1g, acc, 1, wm, wn, lq, lr, s_g);
            __syncthreads();
            if (tid < 128) {
                const float g0 = s_g[0][0][tid] + s_g[0][1][tid];
                const float g1 = s_g[1][0][tid] + s_g[1][1][tid];
                s_sc[0][tid] = 1.f + 1.f / (1.f + expf(-g0));
                s_sc[1][tid] = 1.f + 1.f / (1.f + expf(-g1));
            }
            __syncthreads();
#pragma unroll
            for (int mt = 0; mt < 2; ++mt) {
                sc[mt][0] = s_sc[0][wm * 32 + mt * 16 + lq];
                sc[mt][1] = s_sc[0][wm * 32 + mt * 16 + lq + 8];
            }
            zero_acc(acc);
        }
        if (j == 23) {                         // switch scales s0 -> s1
#pragma unroll
            for (int mt = 0; mt < 2; ++mt) {
                sc[mt][0] = s_sc[1][wm * 32 + mt * 16 + lq];
                sc[mt][1] = s_sc[1][wm * 32 + mt * 16 + lq + 8];
            }
        }
    }

    // epilogue: out = s0*(X0@W1) + s1*(X1@W2) accumulated in acc
#pragma unroll
    for (int mt = 0; mt < 2; ++mt) {
        const int r0 = wm * 32 + mt * 16 + lq;
#pragma unroll
        for (int nt = 0; nt < 16; ++nt) {
            const int cb = wn * 128 + nt * 8 + lr * 2;
            float2 v0 = make_float2(acc[mt][nt][0], acc[mt][nt][1]);
            float2 v1 = make_float2(acc[mt][nt][2], acc[mt][nt][3]);
            *reinterpret_cast<float2*>(out + (rowbase + r0) * DIM + cb) = v0;
            *reinterpret_cast<float2*>(out + (rowbase + r0 + 8) * DIM + cb) = v1;
        }
    }
}

// prep: g_Wt[z][n*GW + k] = tf32_rna(W_z[k][n])
__global__ void wprep_kernel(const float* __restrict__ w1, const float* __restrict__ w2,
                             const float* __restrict__ a1, const float* __restrict__ a2) {
    const int z = blockIdx.x;
    const float* src = (z == 0) ? a1 : (z == 1) ? a2 : (z == 2) ? w1 : w2;
    const int n = threadIdx.x;
    const int k0 = blockIdx.y * 32;
    for (int k = k0; k < k0 + 32; ++k) {
        float v = src[k * DIM + n];
        g_Wt[z][n * GW + k] = __uint_as_float(to_tf32(v));
    }
}

extern "C" void kernel_launch(void* const* d_in, const int* in_sizes, int n_in,
                              void* d_out, int out_size) {
    const float* i0 = (const float*)d_in[0];
    const float* i1 = (const float*)d_in[1];
    const float* W1 = (const float*)d_in[2];
    const float* W2 = (const float*)d_in[3];
    const float* A1 = (const float*)d_in[4];
    const float* A2 = (const float*)d_in[5];
    float* out = (float*)d_out;

    wprep_kernel<<<dim3(4, 8), 256>>>(W1, W2, A1, A2);

    cudaFuncSetAttribute(fused_mma_kernel,
                         cudaFuncAttributeMaxDynamicSharedMemorySize, SMEM_BYTES);
    const int rows = in_sizes[0] / DIM;          // 65536
    fused_mma_kernel<<<rows / TM, THREADS, SMEM_BYTES>>>(i0, i1, out);
    (void)n_in; (void)out_size;
}

// round 7
// speedup vs baseline: 1.1957x; 1.1957x over previous
#include <cuda_runtime.h>
#include <cstdint>
#include <math.h>

#define DIM 256
#define TM 64
#define THREADS 256
#define KC 32
#define NJOBS 32                 // 4 passes x 8 chunks

#define PX 36                    // smem row stride (floats): 36%32==4 -> LDSM conflict-free
#define PW 36
#define GW 256                   // g_Wt gmem row stride
#define XS_FLOATS (TM * PX)      // 2304
#define WS_FLOATS (256 * PW)     // 9216
#define BUF_FLOATS (XS_FLOATS + WS_FLOATS)      // 11520 -> 46080 B
#define BUF_BYTES (BUF_FLOATS * 4)
#define SMEM_BYTES (2 * BUF_BYTES)              // 92160 B -> 2 CTAs/SM

__device__ float g_Wt[4][256 * GW];   // [n][k], transposed + tf32-rna-rounded

__device__ __forceinline__ uint32_t smem_u32(const void* p) {
    uint32_t a;
    asm("{ .reg .u64 t; cvta.to.shared.u64 t, %1; cvt.u32.u64 %0, t; }" : "=r"(a) : "l"(p));
    return a;
}
__device__ __forceinline__ void cp16(uint32_t s, const float* g) {
    asm volatile("cp.async.cg.shared.global [%0], [%1], 16;" :: "r"(s), "l"(g));
}
#define CP_COMMIT() asm volatile("cp.async.commit_group;" ::: "memory")
#define CP_WAIT(n)  asm volatile("cp.async.wait_group %0;" :: "n"(n) : "memory")

__device__ __forceinline__ uint32_t to_tf32(float x) {
    uint32_t r;
    asm("cvt.rna.tf32.f32 %0, %1;" : "=r"(r) : "f"(x));
    return r;
}
__device__ __forceinline__ void ldsm4(uint32_t* r, uint32_t addr) {
    asm volatile("ldmatrix.sync.aligned.m8n8.x4.shared.b16 {%0,%1,%2,%3}, [%4];"
                 : "=r"(r[0]), "=r"(r[1]), "=r"(r[2]), "=r"(r[3]) : "r"(addr));
}
__device__ __forceinline__ void mma8(float* c, const uint32_t* a, const uint32_t* b) {
    asm volatile(
        "mma.sync.aligned.m16n8k8.row.col.f32.tf32.tf32.f32 "
        "{%0,%1,%2,%3}, {%4,%5,%6,%7}, {%8,%9}, {%0,%1,%2,%3};"
        : "+f"(c[0]), "+f"(c[1]), "+f"(c[2]), "+f"(c[3])
        : "r"(a[0]), "r"(a[1]), "r"(a[2]), "r"(a[3]), "r"(b[0]), "r"(b[1]));
}

// ---- one KC=32 chunk: acc(32x64 warptile) += X @ W ----
template <bool SCALE>
__device__ __forceinline__ void gemm_chunk(uint32_t a_base, uint32_t b_base,
                                           float (&acc)[2][8][4],
                                           const float (&sc)[2][2]) {
#pragma unroll
    for (int ks = 0; ks < 4; ++ks) {
        uint32_t ua[2][4];
        ldsm4(ua[0], a_base + ks * 32);
        ldsm4(ua[1], a_base + 16 * PX * 4 + ks * 32);
        if (SCALE) {
#pragma unroll
            for (int mt = 0; mt < 2; ++mt) {
                ua[mt][0] = __float_as_uint(__uint_as_float(ua[mt][0]) * sc[mt][0]);
                ua[mt][1] = __float_as_uint(__uint_as_float(ua[mt][1]) * sc[mt][1]);
                ua[mt][2] = __float_as_uint(__uint_as_float(ua[mt][2]) * sc[mt][0]);
                ua[mt][3] = __float_as_uint(__uint_as_float(ua[mt][3]) * sc[mt][1]);
            }
        }
#pragma unroll
        for (int nt2 = 0; nt2 < 4; ++nt2) {
            uint32_t b[4];                         // nt = 2*nt2, 2*nt2+1
            ldsm4(b, b_base + nt2 * (16 * PW * 4) + ks * 32);
            mma8(acc[0][2 * nt2],     ua[0], b);
            mma8(acc[1][2 * nt2],     ua[1], b);
            mma8(acc[0][2 * nt2 + 1], ua[0], b + 2);
            mma8(acc[1][2 * nt2 + 1], ua[1], b + 2);
        }
    }
}

__device__ __forceinline__ void zero_acc(float (&acc)[2][8][4]) {
#pragma unroll
    for (int mt = 0; mt < 2; ++mt)
#pragma unroll
        for (int nt = 0; nt < 8; ++nt)
#pragma unroll
            for (int q = 0; q < 4; ++q) acc[mt][nt][q] = 0.f;
}

__device__ __forceinline__ void gate_dot(const float* __restrict__ Xo,
                                         const float (&acc)[2][8][4], int g,
                                         int wm, int wn, int lq, int lr,
                                         float (*s_g)[4][TM]) {
    float pr[2][2] = {{0.f, 0.f}, {0.f, 0.f}};
#pragma unroll
    for (int mt = 0; mt < 2; ++mt) {
        const int r0 = wm * 32 + mt * 16 + lq;
#pragma unroll
        for (int nt = 0; nt < 8; ++nt) {
            const int cb = wn * 64 + nt * 8 + lr * 2;
            float2 v0 = *reinterpret_cast<const float2*>(Xo + (size_t)r0 * DIM + cb);
            float2 v1 = *reinterpret_cast<const float2*>(Xo + (size_t)(r0 + 8) * DIM + cb);
            pr[mt][0] += acc[mt][nt][0] * v0.x + acc[mt][nt][1] * v0.y;
            pr[mt][1] += acc[mt][nt][2] * v1.x + acc[mt][nt][3] * v1.y;
        }
    }
#pragma unroll
    for (int off = 1; off <= 2; off <<= 1)
#pragma unroll
        for (int mt = 0; mt < 2; ++mt) {
            pr[mt][0] += __shfl_xor_sync(0xFFFFFFFFu, pr[mt][0], off);
            pr[mt][1] += __shfl_xor_sync(0xFFFFFFFFu, pr[mt][1], off);
        }
    if (lr == 0) {
#pragma unroll
        for (int mt = 0; mt < 2; ++mt) {
            s_g[g][wn][wm * 32 + mt * 16 + lq] = pr[mt][0];
            s_g[g][wn][wm * 32 + mt * 16 + lq + 8] = pr[mt][1];
        }
    }
}

__global__ void __launch_bounds__(THREADS, 2)
fused_mma_kernel(const float* __restrict__ i0, const float* __restrict__ i1,
                 float* __restrict__ out) {
    extern __shared__ float dyn[];
    __shared__ float s_g[2][4][TM];
    __shared__ float s_sc[2][TM];

    const int tid = threadIdx.x;
    const int l = tid & 31, w = tid >> 5;
    const int wm = w >> 2, wn = w & 3;         // m-split 2, n-split 4
    const int lq = l >> 2, lr = l & 3;
    const size_t rowbase = (size_t)blockIdx.x * TM;
    const float* X0g = i0 + rowbase * DIM;
    const float* X1g = i1 + rowbase * DIM;
    const uint32_t sb = smem_u32(dyn);

    // per-lane LDSM addressing
    const int arow = ((l >> 3) & 1) * 8 + (l & 7);
    const int acg  = (l >> 4) & 1;
    const int brow = ((l >> 4) & 1) * 8 + (l & 7);
    const int bcg  = (l >> 3) & 1;
    const uint32_t a_off = (uint32_t)((wm * 32 + arow) * PX + acg * 4) * 4;
    const uint32_t b_off = (uint32_t)(XS_FLOATS + (wn * 64 + brow) * PW + bcg * 4) * 4;

    // jobs 0..31: pass p=j>>3, chunk c=j&7
    //  p0: A=X1,B=attn1 -> g0 dot X0    p1: A=X0,B=attn2 -> g1 dot X1
    //  p2: A=X0,B=W1 (scale s0)         p3: A=X1,B=W2 (scale s1)
    auto stage = [&](int j) {
        const int p = j >> 3, c = j & 7;
        const float* As = (p == 0 || p == 3) ? X1g : X0g;
        const float* Bs = g_Wt[p];
        const uint32_t base = sb + (uint32_t)(j & 1) * BUF_BYTES;
#pragma unroll
        for (int t = 0; t < 2; ++t) {          // X chunk: 64 x 32
            const int id = tid + t * THREADS;
            const int r = id >> 3, c4 = (id & 7) << 2;
            cp16(base + (uint32_t)(r * PX + c4) * 4, As + (size_t)r * DIM + c * 32 + c4);
        }
#pragma unroll
        for (int t = 0; t < 8; ++t) {          // Wt chunk: 256 n x 32 k
            const int id = tid + t * THREADS;
            const int n = id >> 3, k4 = (id & 7) << 2;
            cp16(base + (uint32_t)(XS_FLOATS + n * PW + k4) * 4,
                 Bs + (size_t)n * GW + c * 32 + k4);
        }
        CP_COMMIT();
    };

    float acc[2][8][4];
    zero_acc(acc);
    float sc[2][2] = {{1.f, 1.f}, {1.f, 1.f}};

    stage(0);
    stage(1);

    for (int j = 0; j < NJOBS; ++j) {
        if (j == NJOBS - 1) { CP_WAIT(0); } else { CP_WAIT(1); }
        __syncthreads();
        const uint32_t base = sb + (uint32_t)(j & 1) * BUF_BYTES;
        if (j >= 16) gemm_chunk<true>(base + a_off, base + b_off, acc, sc);
        else         gemm_chunk<false>(base + a_off, base + b_off, acc, sc);

        if (j == 7) {                          // g0 = rowdot(U0, X0)
            gate_dot(X0g, acc, 0, wm, wn, lq, lr, s_g);
            zero_acc(acc);
        }
        if (j == 15) {                         // g1; sigmoid; load s0 scales
            gate_dot(X1g, acc, 1, wm, wn, lq, lr, s_g);
            __syncthreads();
            if (tid < TM) {
                const float g0 = s_g[0][0][tid] + s_g[0][1][tid] + s_g[0][2][tid] + s_g[0][3][tid];
                const float g1 = s_g[1][0][tid] + s_g[1][1][tid] + s_g[1][2][tid] + s_g[1][3][tid];
                s_sc[0][tid] = 1.f + 1.f / (1.f + expf(-g0));
                s_sc[1][tid] = 1.f + 1.f / (1.f + expf(-g1));
            }
            __syncthreads();
#pragma unroll
            for (int mt = 0; mt < 2; ++mt) {
                sc[mt][0] = s_sc[0][wm * 32 + mt * 16 + lq];
                sc[mt][1] = s_sc[0][wm * 32 + mt * 16 + lq + 8];
            }
            zero_acc(acc);
        }
        if (j == 23) {                         // switch scales s0 -> s1
#pragma unroll
            for (int mt = 0; mt < 2; ++mt) {
                sc[mt][0] = s_sc[1][wm * 32 + mt * 16 + lq];
                sc[mt][1] = s_sc[1][wm * 32 + mt * 16 + lq + 8];
            }
        }
        __syncthreads();                       // all reads of buf j done
        if (j + 2 < NJOBS) stage(j + 2);
    }

    // epilogue: out = s0*(X0@W1) + s1*(X1@W2) accumulated in acc
#pragma unroll
    for (int mt = 0; mt < 2; ++mt) {
        const int r0 = wm * 32 + mt * 16 + lq;
#pragma unroll
        for (int nt = 0; nt < 8; ++nt) {
            const int cb = wn * 64 + nt * 8 + lr * 2;
            float2 v0 = make_float2(acc[mt][nt][0], acc[mt][nt][1]);
            float2 v1 = make_float2(acc[mt][nt][2], acc[mt][nt][3]);
            *reinterpret_cast<float2*>(out + (rowbase + r0) * DIM + cb) = v0;
            *reinterpret_cast<float2*>(out + (rowbase + r0 + 8) * DIM + cb) = v1;
        }
    }
}

// prep: g_Wt[z][n*GW + k] = tf32_rna(W_z[k][n])
__global__ void wprep_kernel(const float* __restrict__ w1, const float* __restrict__ w2,
                             const float* __restrict__ a1, const float* __restrict__ a2) {
    const int z = blockIdx.x;
    const float* src = (z == 0) ? a1 : (z == 1) ? a2 : (z == 2) ? w1 : w2;
    const int n = threadIdx.x;
    const int k0 = blockIdx.y * 32;
    for (int k = k0; k < k0 + 32; ++k) {
        float v = src[k * DIM + n];
        g_Wt[z][n * GW + k] = __uint_as_float(to_tf32(v));
    }
}

extern "C" void kernel_launch(void* const* d_in, const int* in_sizes, int n_in,
                              void* d_out, int out_size) {
    const float* i0 = (const float*)d_in[0];
    const float* i1 = (const float*)d_in[1];
    const float* W1 = (const float*)d_in[2];
    const float* W2 = (const float*)d_in[3];
    const float* A1 = (const float*)d_in[4];
    const float* A2 = (const float*)d_in[5];
    float* out = (float*)d_out;

    wprep_kernel<<<dim3(4, 8), 256>>>(W1, W2, A1, A2);

    cudaFuncSetAttribute(fused_mma_kernel,
                         cudaFuncAttributeMaxDynamicSharedMemorySize, SMEM_BYTES);
    const int rows = in_sizes[0] / DIM;          // 65536
    fused_mma_kernel<<<rows / TM, THREADS, SMEM_BYTES>>>(i0, i1, out);
    (void)n_in; (void)out_size;
}